// round 14
// baseline (speedup 1.0000x reference)
#include <cuda_runtime.h>
#include <cstdint>

// Spatial correlation sampler: out[b][dy][dx][y][x] =
//   sum_c in1[b,c,y,x] * in2[b,c,y+dy-4,x+dx-4]   (zero padded), dy,dx in 0..8
//
// Round-14: all-produce variant of r13. No dedicated producer warp: all 9
// warps fill (3-4 cp.async each per stage) AND consume. 288 thr x 2 blocks
// lifts the reg cap 102 -> 113, funding an explicit one-channel operand
// prefetch (next channel's 8 LDS issue before this channel's 27 FFMA2),
// hiding smem latency for 3 of 4 channels per stage.
// mbarrier slot protocol as r13 (full: noinc cp.async arrive from all 288;
// empty: release-arrive from all 288 after consumption).

#define CC 128
#define HH 96
#define WW 128
#define HW (HH * WW)

#define NTHR    288          // 9 warps, all produce + consume
#define CHPS    4            // channels per stage
#define STAGES  (CC / CHPS)  // 32
#define NBUF    4
#define W2H     72           // in2 smem row: 4 + 64 + 4 floats
#define W1H     64           // in1 smem row floats
#define CHFH    (3 * W2H + 11 * W1H)   // 920 floats per channel slab
#define BUFF    (CHPS * CHFH)          // floats per slot
#define BUFB    (BUFF * 4)             // 14720 B per slot
#define SMEMB   (NBUF * BUFB)          // 58880 B
#define NCHUNK  (CHPS * 227)           // 908 16B chunks per stage

typedef unsigned long long ull;

__device__ __forceinline__ void fma2(ull& acc, ull a, ull b) {
    asm("fma.rn.f32x2 %0, %1, %2, %0;" : "+l"(acc) : "l"(a), "l"(b));
}

__device__ __forceinline__ ull pkmid(ull a, ull b) {
    ull r;
    asm("{ .reg .b32 al, ah, bl, bh;\n\t"
        "  mov.b64 {al, ah}, %1;\n\t"
        "  mov.b64 {bl, bh}, %2;\n\t"
        "  mov.b64 %0, {ah, bl}; }"
        : "=l"(r) : "l"(a), "l"(b));
    return r;
}

__device__ __forceinline__ float2 unpk(ull v) {
    unsigned lo, hi;
    asm("mov.b64 {%0,%1}, %2;" : "=r"(lo), "=r"(hi) : "l"(v));
    return make_float2(__uint_as_float(lo), __uint_as_float(hi));
}

__device__ __forceinline__ void cp16(uint32_t dst, const float* src) {
    asm volatile("cp.async.cg.shared.global [%0], [%1], 16;"
                 :: "r"(dst), "l"(src) : "memory");
}

__device__ __forceinline__ void mbar_init(uint32_t a, uint32_t cnt) {
    asm volatile("mbarrier.init.shared.b64 [%0], %1;" :: "r"(a), "r"(cnt)
                 : "memory");
}
__device__ __forceinline__ void mbar_arrive(uint32_t a) {
    asm volatile("mbarrier.arrive.release.cta.shared::cta.b64 _, [%0];"
                 :: "r"(a) : "memory");
}
__device__ __forceinline__ void cp_arrive_noinc(uint32_t a) {
    asm volatile("cp.async.mbarrier.arrive.noinc.shared::cta.b64 [%0];"
                 :: "r"(a) : "memory");
}
__device__ __forceinline__ void mbar_wait(uint32_t a, uint32_t ph) {
    uint32_t done;
    do {
        asm volatile(
            "{ .reg .pred p;\n\t"
            "mbarrier.try_wait.parity.acquire.cta.shared::cta.b64 p, [%1], %2, 0x989680;\n\t"
            "selp.b32 %0, 1, 0, p; }"
            : "=r"(done) : "r"(a), "r"(ph) : "memory");
    } while (!done);
}

__device__ __forceinline__ int clampi(int v, int lo, int hi) {
    return v < lo ? lo : (v > hi ? hi : v);
}

struct Ops { ull u0, u1, u2, u3, u4, A0, A1, A2; };

__global__ __launch_bounds__(NTHR, 2) void corr_kernel(
    const float* __restrict__ in1,
    const float* __restrict__ in2,
    float* __restrict__ out)
{
    extern __shared__ float sm[];
    __shared__ ull mbar[2 * NBUF];       // [0..3]=full, [4..7]=empty

    const int tid  = threadIdx.x;
    const int lane = tid & 31;
    const int w    = tid >> 5;            // 0..8
    const int g    = w % 3;               // dy group: dy = 3g..3g+2
    const int ri   = w / 3;               // in2 row of the tile
    const int b    = blockIdx.y;
    const int r0   = blockIdx.x * 3 - 4;
    const int r    = r0 + ri;
    const int xoff = blockIdx.z * 64;     // x half
    const int lhalf = (xoff == 0);
    const int x0g  = xoff + 2 * lane;

    const float rowok = (r >= 0 && r < HH) ? 1.0f : 0.0f;

    const float* p1base = in1 + (size_t)b * CC * HW;
    const float* p2base = in2 + (size_t)b * CC * HW;
    const uint32_t smb  = (uint32_t)__cvta_generic_to_shared(sm);
    const uint32_t mbb  = (uint32_t)__cvta_generic_to_shared(mbar);

    // ---- init mbarriers + zero OOB pad chunks ----
    if (tid < NBUF) {
        mbar_init(mbb + tid * 8, NTHR);              // full: 288 noinc arrivals
        mbar_init(mbb + (NBUF + tid) * 8, NTHR);     // empty: 288 arrivals
    }
    if (tid < 192) {   // 4 bufs x 4 ch x 3 rows x 4 floats
        const int bu = tid / 48, q = tid % 48;
        const int ch = q / 12, q2 = q % 12;
        const int rr = q2 / 4, f = q2 & 3;
        sm[(size_t)bu * BUFF + ch * CHFH + rr * W2H + (lhalf ? f : 68 + f)] = 0.0f;
    }

    // ---- precompute fill slots: 908 chunks / 288 threads (<=4 each) ----
    const float* ssrc[4];
    uint32_t     sdst[4];
    const int nslots = (tid < NCHUNK - 3 * NTHR) ? 4 : 3;   // 4 for tid<44
    #pragma unroll
    for (int j = 0; j < 4; j++) {
        const int n = tid + NTHR * j;
        if (n < NCHUNK) {
            const int ch = n / 227, rem = n % 227;
            if (rem < 51) {               // in2: 3 rows x 17 valid chunks
                const int rr = rem / 17, c = rem % 17;
                const int cc = c + lhalf;
                const int srow = clampi(r0 + rr, 0, HH - 1);
                ssrc[j] = p2base + (size_t)ch * HW + (size_t)srow * WW
                          + (xoff - 4 + 4 * cc);
                sdst[j] = smb + ((ch * CHFH + rr * W2H + 4 * cc) << 2);
            } else {                      // in1: 11 rows x 16 chunks
                const int rem2 = rem - 51;
                const int rw = rem2 >> 4, k = rem2 & 15;
                const int srow = clampi(r0 - 4 + rw, 0, HH - 1);
                ssrc[j] = p1base + (size_t)ch * HW + (size_t)srow * WW
                          + (xoff + 4 * k);
                sdst[j] = smb + ((ch * CHFH + 216 + rw * W1H + 4 * k) << 2);
            }
        }
    }
    __syncthreads();   // orders mbarrier init + pad zeroing; loop barrier-free

    #define FILL(F)                                                       \
        do {                                                               \
            const size_t co = (size_t)(CHPS * (F)) * HW;                   \
            const uint32_t bo = (uint32_t)((F) & 3) * BUFB;                \
            _Pragma("unroll")                                              \
            for (int j = 0; j < 4; j++)                                    \
                if (j < nslots) cp16(sdst[j] + bo, ssrc[j] + co);          \
            cp_arrive_noinc(mbb + ((F) & 3) * 8);                          \
        } while (0)

    ull acc[3][9];
    #pragma unroll
    for (int t = 0; t < 3; t++)
        #pragma unroll
        for (int d = 0; d < 9; d++)
            acc[t][d] = 0ull;

    const int jbase = ri + 8 - 3 * g;
    const int winf  = ri * W2H + 2 * lane;
    const int af0   = 216 + jbase * W1H + 2 * lane;

    #define LOADOPS(B, CB)                                                 \
        do {                                                               \
            const float* _wb = (CB) + winf;                                \
            const float* _ab = (CB) + af0;                                 \
            (B).u0 = *(const ull*)(_wb);                                   \
            (B).u1 = *(const ull*)(_wb + 2);                               \
            (B).u2 = *(const ull*)(_wb + 4);                               \
            (B).u3 = *(const ull*)(_wb + 6);                               \
            (B).u4 = *(const ull*)(_wb + 8);                               \
            (B).A0 = *(const ull*)(_ab);                                   \
            (B).A1 = *(const ull*)(_ab - W1H);                             \
            (B).A2 = *(const ull*)(_ab - 2 * W1H);                         \
        } while (0)

    #define COMPUTE(B)                                                     \
        do {                                                               \
            ull wp[9];                                                     \
            wp[0] = (B).u0;  wp[2] = (B).u1;  wp[4] = (B).u2;              \
            wp[6] = (B).u3;  wp[8] = (B).u4;                               \
            wp[1] = pkmid((B).u0, (B).u1);                                 \
            wp[3] = pkmid((B).u1, (B).u2);                                 \
            wp[5] = pkmid((B).u2, (B).u3);                                 \
            wp[7] = pkmid((B).u3, (B).u4);                                 \
            _Pragma("unroll")                                              \
            for (int d = 0; d < 9; d++) {                                  \
                fma2(acc[0][d], (B).A0, wp[d]);                            \
                fma2(acc[1][d], (B).A1, wp[d]);                            \
                fma2(acc[2][d], (B).A2, wp[d]);                            \
            }                                                              \
        } while (0)

    // prologue: fill slots 0..2 (use 0 -> no empty wait)
    FILL(0);
    FILL(1);
    FILL(2);

    #pragma unroll 1
    for (int s = 0; s < STAGES; s++) {
        const int slot = s & 3;
        mbar_wait(mbb + slot * 8, (s >> 2) & 1);

        const float* bufbase = sm + slot * BUFF;

        // channel pipeline: next channel's LDS issue before this channel's FMAs
        Ops P;
        LOADOPS(P, bufbase);
        #pragma unroll
        for (int u = 0; u < CHPS; u++) {
            if (u + 1 < CHPS) {
                Ops N;
                LOADOPS(N, bufbase + (u + 1) * CHFH);
                COMPUTE(P);
                P = N;
            } else {
                COMPUTE(P);
            }
        }
        mbar_arrive(mbb + (NBUF + slot) * 8);   // release this slot

        const int f = s + 3;
        if (f < STAGES) {
            const int use = f >> 2;
            if (use > 0)
                mbar_wait(mbb + (NBUF + (f & 3)) * 8, (use - 1) & 1);
            FILL(f);
        }
    }
    #undef FILL
    #undef LOADOPS
    #undef COMPUTE

    // ---- epilogue ----
    #pragma unroll
    for (int t = 0; t < 3; t++) {
        const int y = r + 4 - (3 * g + t);
        if (y < 0 || y >= HH) continue;        // warp-uniform
        const int dy = 3 * g + t;
        #pragma unroll
        for (int d = 0; d < 9; d++) {
            const float2 v = unpk(acc[t][d]);
            float* po = out + (((((size_t)b * 9 + dy) * 9 + d) * HH + y) * WW) + x0g;
            *(float2*)po = make_float2(v.x * rowok, v.y * rowok);
        }
    }
}

extern "C" void kernel_launch(void* const* d_in, const int* in_sizes, int n_in,
                              void* d_out, int out_size)
{
    const float* in1 = (const float*)d_in[0];
    const float* in2 = (const float*)d_in[1];
    float* out = (float*)d_out;

    cudaFuncSetAttribute(corr_kernel,
                         cudaFuncAttributeMaxDynamicSharedMemorySize, SMEMB);

    // x = r-tile (35 tiles cover r=-4..100), y = batch, z = x-half
    dim3 grid(35, 8, 2);
    corr_kernel<<<grid, NTHR, SMEMB>>>(in1, in2, out);
}

// round 15
// speedup vs baseline: 1.0316x; 1.0316x over previous
#include <cuda_runtime.h>
#include <cstdint>

// Spatial correlation sampler: out[b][dy][dx][y][x] =
//   sum_c in1[b,c,y,x] * in2[b,c,y+dy-4,x+dx-4]   (zero padded), dy,dx in 0..8
//
// Round-15 = round-13 (warp-specialized producer/consumer, mbarrier slots)
// + ONE change: consumer warps walk a stage's 4 channel slabs in rotated
// order (u+w)&3, interleaving LDS bursts and FMA blocks across warps so the
// smem crossbar and the fma pipe run concurrently instead of alternating.

#define CC 128
#define HH 96
#define WW 128
#define HW (HH * WW)

#define NTHR    320          // warps 0..8 consume, warp 9 produces
#define NCW     9            // consumer warps
#define CHPS    4            // channels per stage
#define STAGES  (CC / CHPS)  // 32
#define NBUF    4
#define W2H     72           // in2 smem row: 4 + 64 + 4 floats
#define W1H     64           // in1 smem row floats
#define CHFH    (3 * W2H + 11 * W1H)   // 920 floats per channel slab
#define CHFHB   (CHFH * 4)             // 3680 B
#define BUFF    (CHPS * CHFH)          // floats per slot
#define BUFB    (BUFF * 4)             // 14720 B per slot
#define SMEMB   (NBUF * BUFB)          // 58880 B

typedef unsigned long long ull;

__device__ __forceinline__ void fma2(ull& acc, ull a, ull b) {
    asm("fma.rn.f32x2 %0, %1, %2, %0;" : "+l"(acc) : "l"(a), "l"(b));
}

__device__ __forceinline__ ull pkmid(ull a, ull b) {
    ull r;
    asm("{ .reg .b32 al, ah, bl, bh;\n\t"
        "  mov.b64 {al, ah}, %1;\n\t"
        "  mov.b64 {bl, bh}, %2;\n\t"
        "  mov.b64 %0, {ah, bl}; }"
        : "=l"(r) : "l"(a), "l"(b));
    return r;
}

__device__ __forceinline__ float2 unpk(ull v) {
    unsigned lo, hi;
    asm("mov.b64 {%0,%1}, %2;" : "=r"(lo), "=r"(hi) : "l"(v));
    return make_float2(__uint_as_float(lo), __uint_as_float(hi));
}

__device__ __forceinline__ void cp16(uint32_t dst, const float* src) {
    asm volatile("cp.async.cg.shared.global [%0], [%1], 16;"
                 :: "r"(dst), "l"(src) : "memory");
}

__device__ __forceinline__ void mbar_init(uint32_t a, uint32_t cnt) {
    asm volatile("mbarrier.init.shared.b64 [%0], %1;" :: "r"(a), "r"(cnt)
                 : "memory");
}
__device__ __forceinline__ void mbar_arrive(uint32_t a) {
    asm volatile("mbarrier.arrive.release.cta.shared::cta.b64 _, [%0];"
                 :: "r"(a) : "memory");
}
__device__ __forceinline__ void cp_arrive_noinc(uint32_t a) {
    asm volatile("cp.async.mbarrier.arrive.noinc.shared::cta.b64 [%0];"
                 :: "r"(a) : "memory");
}
__device__ __forceinline__ void mbar_wait(uint32_t a, uint32_t ph) {
    uint32_t done;
    do {
        asm volatile(
            "{ .reg .pred p;\n\t"
            "mbarrier.try_wait.parity.acquire.cta.shared::cta.b64 p, [%1], %2, 0x989680;\n\t"
            "selp.b32 %0, 1, 0, p; }"
            : "=r"(done) : "r"(a), "r"(ph) : "memory");
    } while (!done);
}

__device__ __forceinline__ int clampi(int v, int lo, int hi) {
    return v < lo ? lo : (v > hi ? hi : v);
}

__global__ __launch_bounds__(NTHR, 2) void corr_kernel(
    const float* __restrict__ in1,
    const float* __restrict__ in2,
    float* __restrict__ out)
{
    extern __shared__ float sm[];
    __shared__ ull mbar[2 * NBUF];       // [0..3]=full, [4..7]=empty

    const int tid  = threadIdx.x;
    const int lane = tid & 31;
    const int w    = tid >> 5;            // 0..9
    const int b    = blockIdx.y;
    const int r0   = blockIdx.x * 3 - 4;
    const int xoff = blockIdx.z * 64;     // x half
    const int lhalf = (xoff == 0);

    const float* p1base = in1 + (size_t)b * CC * HW;
    const float* p2base = in2 + (size_t)b * CC * HW;
    const uint32_t smb  = (uint32_t)__cvta_generic_to_shared(sm);
    const uint32_t mbb  = (uint32_t)__cvta_generic_to_shared(mbar);

    // ---- init mbarriers + zero OOB pad chunks (before pipeline) ----
    if (tid < NBUF) {
        mbar_init(mbb + tid * 8, 32);                // full: 32 producer lanes
        mbar_init(mbb + (NBUF + tid) * 8, NCW * 32); // empty: 288 consumers
    }
    if (tid < 192) {   // 4 bufs x 4 ch x 3 rows x 4 floats
        const int bu = tid / 48, q = tid % 48;
        const int ch = q / 12, q2 = q % 12;
        const int rr = q2 / 4, f = q2 & 3;
        sm[(size_t)bu * BUFF + ch * CHFH + rr * W2H + (lhalf ? f : 68 + f)] = 0.0f;
    }
    __syncthreads();   // once; main loop is barrier-free

    if (w == NCW) {
        // ================= PRODUCER WARP =================
        // 227 chunks per channel: 51 in2 (3x17 valid) + 176 in1 (11x16).
        const float* srcp[8];
        uint32_t     dstb[8];          // byte offset within a channel slab
        const int nj = (lane < 3) ? 8 : 7;   // 227 = 7*32 + 3
        #pragma unroll
        for (int j = 0; j < 8; j++) {
            const int n = lane + 32 * j;
            if (n < 227) {
                if (n < 51) {
                    const int rr = n / 17, c = n % 17;
                    const int cc = c + lhalf;
                    const int srow = clampi(r0 + rr, 0, HH - 1);
                    srcp[j] = p2base + (size_t)srow * WW + (xoff - 4 + 4 * cc);
                    dstb[j] = (uint32_t)((rr * W2H + 4 * cc) << 2);
                } else {
                    const int n2 = n - 51;
                    const int rw = n2 >> 4, k = n2 & 15;
                    const int srow = clampi(r0 - 4 + rw, 0, HH - 1);
                    srcp[j] = p1base + (size_t)srow * WW + (xoff + 4 * k);
                    dstb[j] = (uint32_t)((216 + rw * W1H + 4 * k) << 2);
                }
            }
        }

        #pragma unroll 1
        for (int s = 0; s < STAGES; s++) {
            const int slot = s & 3;
            const int use  = s >> 2;
            if (use > 0)
                mbar_wait(mbb + (NBUF + slot) * 8, (use - 1) & 1);

            const uint32_t bo = smb + slot * BUFB;
            #pragma unroll
            for (int ch = 0; ch < CHPS; ch++) {
                const size_t co = (size_t)(CHPS * s + ch) * HW;
                const uint32_t bc = bo + ch * CHFHB;
                #pragma unroll
                for (int j = 0; j < 8; j++)
                    if (j < nj) cp16(bc + dstb[j], srcp[j] + co);
            }
            cp_arrive_noinc(mbb + slot * 8);   // deferred, counts vs init=32
        }
    } else {
        // ================= CONSUMER WARPS =================
        const int g  = w % 3;            // dy group: dy = 3g..3g+2
        const int ri = w / 3;            // in2 row of the tile
        const int r  = r0 + ri;
        const int x0g = xoff + 2 * lane;
        const float rowok = (r >= 0 && r < HH) ? 1.0f : 0.0f;

        const int jbase = ri + 8 - 3 * g;
        const int winf  = ri * W2H + 2 * lane;
        const int af0   = 216 + jbase * W1H + 2 * lane;

        ull acc[3][9];
        #pragma unroll
        for (int t = 0; t < 3; t++)
            #pragma unroll
            for (int d = 0; d < 9; d++)
                acc[t][d] = 0ull;

        #pragma unroll 1
        for (int s = 0; s < STAGES; s++) {
            const int slot = s & 3;
            mbar_wait(mbb + slot * 8, (s >> 2) & 1);

            const float* bufbase = sm + slot * BUFF;
            #pragma unroll
            for (int u = 0; u < CHPS; u++) {
                // rotated slab order: warps spread across the 4 channel slabs
                const float* base = bufbase + ((u + w) & 3) * CHFH;
                const float* wb = base + winf;
                const float* ab = base + af0;

                const ull u0 = *(const ull*)(wb);
                const ull u1 = *(const ull*)(wb + 2);
                const ull u2 = *(const ull*)(wb + 4);
                const ull u3 = *(const ull*)(wb + 6);
                const ull u4 = *(const ull*)(wb + 8);
                const ull A0 = *(const ull*)(ab);
                const ull A1 = *(const ull*)(ab - W1H);
                const ull A2 = *(const ull*)(ab - 2 * W1H);

                ull wp[9];
                wp[0] = u0;  wp[2] = u1;  wp[4] = u2;  wp[6] = u3;  wp[8] = u4;
                wp[1] = pkmid(u0, u1);
                wp[3] = pkmid(u1, u2);
                wp[5] = pkmid(u2, u3);
                wp[7] = pkmid(u3, u4);

                #pragma unroll
                for (int d = 0; d < 9; d++) {
                    fma2(acc[0][d], A0, wp[d]);
                    fma2(acc[1][d], A1, wp[d]);
                    fma2(acc[2][d], A2, wp[d]);
                }
            }
            mbar_arrive(mbb + (NBUF + slot) * 8);   // release the slot
        }

        // ---- epilogue ----
        #pragma unroll
        for (int t = 0; t < 3; t++) {
            const int y = r + 4 - (3 * g + t);
            if (y < 0 || y >= HH) continue;        // warp-uniform
            const int dy = 3 * g + t;
            #pragma unroll
            for (int d = 0; d < 9; d++) {
                const float2 v = unpk(acc[t][d]);
                float* po = out + (((((size_t)b * 9 + dy) * 9 + d) * HH + y) * WW) + x0g;
                *(float2*)po = make_float2(v.x * rowok, v.y * rowok);
            }
        }
    }
}

extern "C" void kernel_launch(void* const* d_in, const int* in_sizes, int n_in,
                              void* d_out, int out_size)
{
    const float* in1 = (const float*)d_in[0];
    const float* in2 = (const float*)d_in[1];
    float* out = (float*)d_out;

    cudaFuncSetAttribute(corr_kernel,
                         cudaFuncAttributeMaxDynamicSharedMemorySize, SMEMB);

    // x = r-tile (35 tiles cover r=-4..100), y = batch, z = x-half
    dim3 grid(35, 8, 2);
    corr_kernel<<<grid, NTHR, SMEMB>>>(in1, in2, out);
}

// round 16
// speedup vs baseline: 1.1330x; 1.0983x over previous
#include <cuda_runtime.h>
#include <cstdint>

// Spatial correlation sampler: out[b][dy][dx][y][x] =
//   sum_c in1[b,c,y,x] * in2[b,c,y+dy-4,x+dx-4]   (zero padded), dy,dx in 0..8
//
// Round-16 = round-13 (warp-specialized producer/consumer, mbarrier slots) +
//  (1) dead-warp skip: warps whose in2 row r is OOB (outputs all zero) skip
//      the LDS/FMA body and only pace the mbarrier protocol (~7.6% of work);
//  (2) 8 channels per stage, 3 slots (88.3 KB): sync points halved (32->16).

#define CC 128
#define HH 96
#define WW 128
#define HW (HH * WW)

#define NTHR    320          // warps 0..8 consume, warp 9 produces
#define NCW     9            // consumer warps
#define CHPS    8            // channels per stage
#define STAGES  (CC / CHPS)  // 16
#define NBUF    3
#define W2H     72           // in2 smem row: 4 + 64 + 4 floats
#define W1H     64           // in1 smem row floats
#define CHFH    (3 * W2H + 11 * W1H)   // 920 floats per channel slab
#define CHFHB   (CHFH * 4)             // 3680 B
#define BUFF    (CHPS * CHFH)          // floats per slot
#define BUFB    (BUFF * 4)             // 29440 B per slot
#define SMEMB   (NBUF * BUFB)          // 88320 B

typedef unsigned long long ull;

__device__ __forceinline__ void fma2(ull& acc, ull a, ull b) {
    asm("fma.rn.f32x2 %0, %1, %2, %0;" : "+l"(acc) : "l"(a), "l"(b));
}

__device__ __forceinline__ ull pkmid(ull a, ull b) {
    ull r;
    asm("{ .reg .b32 al, ah, bl, bh;\n\t"
        "  mov.b64 {al, ah}, %1;\n\t"
        "  mov.b64 {bl, bh}, %2;\n\t"
        "  mov.b64 %0, {ah, bl}; }"
        : "=l"(r) : "l"(a), "l"(b));
    return r;
}

__device__ __forceinline__ float2 unpk(ull v) {
    unsigned lo, hi;
    asm("mov.b64 {%0,%1}, %2;" : "=r"(lo), "=r"(hi) : "l"(v));
    return make_float2(__uint_as_float(lo), __uint_as_float(hi));
}

__device__ __forceinline__ void cp16(uint32_t dst, const float* src) {
    asm volatile("cp.async.cg.shared.global [%0], [%1], 16;"
                 :: "r"(dst), "l"(src) : "memory");
}

__device__ __forceinline__ void mbar_init(uint32_t a, uint32_t cnt) {
    asm volatile("mbarrier.init.shared.b64 [%0], %1;" :: "r"(a), "r"(cnt)
                 : "memory");
}
__device__ __forceinline__ void mbar_arrive(uint32_t a) {
    asm volatile("mbarrier.arrive.release.cta.shared::cta.b64 _, [%0];"
                 :: "r"(a) : "memory");
}
__device__ __forceinline__ void cp_arrive_noinc(uint32_t a) {
    asm volatile("cp.async.mbarrier.arrive.noinc.shared::cta.b64 [%0];"
                 :: "r"(a) : "memory");
}
__device__ __forceinline__ void mbar_wait(uint32_t a, uint32_t ph) {
    uint32_t done;
    do {
        asm volatile(
            "{ .reg .pred p;\n\t"
            "mbarrier.try_wait.parity.acquire.cta.shared::cta.b64 p, [%1], %2, 0x989680;\n\t"
            "selp.b32 %0, 1, 0, p; }"
            : "=r"(done) : "r"(a), "r"(ph) : "memory");
    } while (!done);
}

__device__ __forceinline__ int clampi(int v, int lo, int hi) {
    return v < lo ? lo : (v > hi ? hi : v);
}

__global__ __launch_bounds__(NTHR, 2) void corr_kernel(
    const float* __restrict__ in1,
    const float* __restrict__ in2,
    float* __restrict__ out)
{
    extern __shared__ float sm[];
    __shared__ ull mbar[2 * NBUF];       // [0..2]=full, [3..5]=empty

    const int tid  = threadIdx.x;
    const int lane = tid & 31;
    const int w    = tid >> 5;            // 0..9
    const int b    = blockIdx.y;
    const int r0   = blockIdx.x * 3 - 4;
    const int xoff = blockIdx.z * 64;     // x half
    const int lhalf = (xoff == 0);

    const float* p1base = in1 + (size_t)b * CC * HW;
    const float* p2base = in2 + (size_t)b * CC * HW;
    const uint32_t smb  = (uint32_t)__cvta_generic_to_shared(sm);
    const uint32_t mbb  = (uint32_t)__cvta_generic_to_shared(mbar);

    // ---- init mbarriers + zero OOB pad chunks (before pipeline) ----
    if (tid < NBUF) {
        mbar_init(mbb + tid * 8, 32);                // full: 32 producer lanes
        mbar_init(mbb + (NBUF + tid) * 8, NCW * 32); // empty: 288 consumers
    }
    if (tid < 288) {   // 3 bufs x 8 ch x 3 rows x 4 floats
        const int bu = tid / 96, q = tid % 96;
        const int ch = q / 12, q2 = q % 12;
        const int rr = q2 / 4, f = q2 & 3;
        sm[(size_t)bu * BUFF + ch * CHFH + rr * W2H + (lhalf ? f : 68 + f)] = 0.0f;
    }
    __syncthreads();   // once; main loop is barrier-free

    if (w == NCW) {
        // ================= PRODUCER WARP =================
        // 227 chunks per channel: 51 in2 (3x17 valid) + 176 in1 (11x16).
        const float* srcp[8];
        uint32_t     dstb[8];          // byte offset within a channel slab
        const int nj = (lane < 3) ? 8 : 7;   // 227 = 7*32 + 3
        #pragma unroll
        for (int j = 0; j < 8; j++) {
            const int n = lane + 32 * j;
            if (n < 227) {
                if (n < 51) {
                    const int rr = n / 17, c = n % 17;
                    const int cc = c + lhalf;
                    const int srow = clampi(r0 + rr, 0, HH - 1);
                    srcp[j] = p2base + (size_t)srow * WW + (xoff - 4 + 4 * cc);
                    dstb[j] = (uint32_t)((rr * W2H + 4 * cc) << 2);
                } else {
                    const int n2 = n - 51;
                    const int rw = n2 >> 4, k = n2 & 15;
                    const int srow = clampi(r0 - 4 + rw, 0, HH - 1);
                    srcp[j] = p1base + (size_t)srow * WW + (xoff + 4 * k);
                    dstb[j] = (uint32_t)((216 + rw * W1H + 4 * k) << 2);
                }
            }
        }

        #pragma unroll 1
        for (int s = 0; s < STAGES; s++) {
            const int slot = s % NBUF;
            const int use  = s / NBUF;
            if (use > 0)
                mbar_wait(mbb + (NBUF + slot) * 8, (use - 1) & 1);

            const uint32_t bo = smb + slot * BUFB;
            #pragma unroll 2
            for (int ch = 0; ch < CHPS; ch++) {
                const size_t co = (size_t)(CHPS * s + ch) * HW;
                const uint32_t bc = bo + ch * CHFHB;
                #pragma unroll
                for (int j = 0; j < 8; j++)
                    if (j < nj) cp16(bc + dstb[j], srcp[j] + co);
            }
            cp_arrive_noinc(mbb + slot * 8);   // deferred, counts vs init=32
        }
    } else {
        // ================= CONSUMER WARPS =================
        const int g  = w % 3;            // dy group: dy = 3g..3g+2
        const int ri = w / 3;            // in2 row of the tile
        const int r  = r0 + ri;
        const int x0g = xoff + 2 * lane;
        const bool alive = (r >= 0 && r < HH);   // warp-uniform

        const int jbase = ri + 8 - 3 * g;
        const int winf  = ri * W2H + 2 * lane;
        const int af0   = 216 + jbase * W1H + 2 * lane;

        ull acc[3][9];
        #pragma unroll
        for (int t = 0; t < 3; t++)
            #pragma unroll
            for (int d = 0; d < 9; d++)
                acc[t][d] = 0ull;

        #pragma unroll 1
        for (int s = 0; s < STAGES; s++) {
            const int slot = s % NBUF;
            mbar_wait(mbb + slot * 8, (s / NBUF) & 1);

            if (alive) {   // dead warps only pace the protocol
                const float* bufbase = sm + slot * BUFF;
                #pragma unroll
                for (int u = 0; u < CHPS; u++) {
                    const float* base = bufbase + u * CHFH;
                    const float* wb = base + winf;
                    const float* ab = base + af0;

                    const ull u0 = *(const ull*)(wb);
                    const ull u1 = *(const ull*)(wb + 2);
                    const ull u2 = *(const ull*)(wb + 4);
                    const ull u3 = *(const ull*)(wb + 6);
                    const ull u4 = *(const ull*)(wb + 8);
                    const ull A0 = *(const ull*)(ab);
                    const ull A1 = *(const ull*)(ab - W1H);
                    const ull A2 = *(const ull*)(ab - 2 * W1H);

                    ull wp[9];
                    wp[0] = u0;  wp[2] = u1;  wp[4] = u2;  wp[6] = u3;
                    wp[8] = u4;
                    wp[1] = pkmid(u0, u1);
                    wp[3] = pkmid(u1, u2);
                    wp[5] = pkmid(u2, u3);
                    wp[7] = pkmid(u3, u4);

                    #pragma unroll
                    for (int d = 0; d < 9; d++) {
                        fma2(acc[0][d], A0, wp[d]);
                        fma2(acc[1][d], A1, wp[d]);
                        fma2(acc[2][d], A2, wp[d]);
                    }
                }
            }
            mbar_arrive(mbb + (NBUF + slot) * 8);   // release the slot
        }

        // ---- epilogue (dead warps write their exact-zero outputs) ----
        #pragma unroll
        for (int t = 0; t < 3; t++) {
            const int y = r + 4 - (3 * g + t);
            if (y < 0 || y >= HH) continue;        // warp-uniform
            const int dy = 3 * g + t;
            #pragma unroll
            for (int d = 0; d < 9; d++) {
                const float2 v = unpk(acc[t][d]);
                float* po = out + (((((size_t)b * 9 + dy) * 9 + d) * HH + y) * WW) + x0g;
                *(float2*)po = make_float2(v.x, v.y);
            }
        }
    }
}

extern "C" void kernel_launch(void* const* d_in, const int* in_sizes, int n_in,
                              void* d_out, int out_size)
{
    const float* in1 = (const float*)d_in[0];
    const float* in2 = (const float*)d_in[1];
    float* out = (float*)d_out;

    cudaFuncSetAttribute(corr_kernel,
                         cudaFuncAttributeMaxDynamicSharedMemorySize, SMEMB);

    // x = r-tile (35 tiles cover r=-4..100), y = batch, z = x-half
    dim3 grid(35, 8, 2);
    corr_kernel<<<grid, NTHR, SMEMB>>>(in1, in2, out);
}